// round 9
// baseline (speedup 1.0000x reference)
#include <cuda_runtime.h>

// ---------------- problem constants (fixed shapes per reference) ----------------
#define IN_H 2048
#define IN_W 2048
#define P1H  1023           // after conv1 (2046) + 2x2 maxpool
#define C2H  1021           // after conv2
#define C3H  1019           // after conv3 / heads
#define NF   (C3H * C3H)    // 1038361 feature-map pixels
#define KTOP 512
#define NSORT 2048

// ---------------- scratch (static __device__, no allocations) -------------------
__device__ float g_out1[10 * P1H * P1H + 64];   // +pad: edge threads read a few cols past row end
__device__ float g_out2[16 * C2H * C2H + 64];
__device__ float g_cand[NF * 6];                // {score, idx(int bits), r0,r1,r2,r3}
__device__ int   g_cnt;

// ---------------- kernel 1: conv1(3x3,3->10) + PReLU + maxpool 2x2 --------------
// Also resets g_cnt (safe: g_cnt is only consumed by later stream-ordered kernels).
__global__ __launch_bounds__(256) void k_conv1(const float* __restrict__ x,
                                               const float* __restrict__ w1,
                                               const float* __restrict__ b1,
                                               const float* __restrict__ p1) {
    if (blockIdx.x == 0 && threadIdx.x == 0) g_cnt = 0;

    __shared__ float sw[270], sb[10], sp[10];
    int tid = threadIdx.x;
    for (int i = tid; i < 270; i += 256) sw[i] = w1[i];
    if (tid < 10) { sb[tid] = b1[tid]; sp[tid] = p1[tid]; }
    __syncthreads();

    int t = blockIdx.x * 256 + tid;
    if (t >= P1H * P1H) return;
    int py = t / P1H, px = t % P1H;
    int iy = py * 2, ix = px * 2;

    float patch[3][4][4];
#pragma unroll
    for (int ic = 0; ic < 3; ic++)
#pragma unroll
        for (int r = 0; r < 4; r++)
#pragma unroll
            for (int c = 0; c < 4; c++)
                patch[ic][r][c] = x[ic * IN_H * IN_W + (iy + r) * IN_W + (ix + c)];

#pragma unroll
    for (int oc = 0; oc < 10; oc++) {
        float a0 = 0.f, a1 = 0.f, a2 = 0.f, a3 = 0.f;
#pragma unroll
        for (int ic = 0; ic < 3; ic++)
#pragma unroll
            for (int ky = 0; ky < 3; ky++)
#pragma unroll
                for (int kx = 0; kx < 3; kx++) {
                    float w = sw[((oc * 3 + ic) * 3 + ky) * 3 + kx];
                    a0 += w * patch[ic][ky][kx];
                    a1 += w * patch[ic][ky][kx + 1];
                    a2 += w * patch[ic][ky + 1][kx];
                    a3 += w * patch[ic][ky + 1][kx + 1];
                }
        float b = sb[oc], p = sp[oc];
        a0 += b; a1 += b; a2 += b; a3 += b;
        a0 = a0 >= 0.f ? a0 : p * a0;
        a1 = a1 >= 0.f ? a1 : p * a1;
        a2 = a2 >= 0.f ? a2 : p * a2;
        a3 = a3 >= 0.f ? a3 : p * a3;
        float m = fmaxf(fmaxf(a0, a1), fmaxf(a2, a3));
        g_out1[oc * P1H * P1H + t] = m;
    }
}

// ---------------- kernel 2: conv2(3x3,10->16) + PReLU (4 px/thread) -------------
// QUADS = ceil(1021/4) = 256 exactly -> shift/mask indexing, better FFMA:LDS ratio.
__global__ __launch_bounds__(256) void k_conv2(const float* __restrict__ w2,
                                               const float* __restrict__ b2,
                                               const float* __restrict__ p2) {
    __shared__ float sw[1440], sb[16], sp[16];
    int tid = threadIdx.x;
    for (int i = tid; i < 1440; i += 256) sw[i] = w2[i];
    if (tid < 16) { sb[tid] = b2[tid]; sp[tid] = p2[tid]; }
    __syncthreads();

    const int QUADS = 256;                 // (C2H + 3) / 4
    int t = blockIdx.x * 256 + tid;
    if (t >= C2H * QUADS) return;
    int y = t >> 8;                        // t / QUADS
    int x0 = (t & 255) * 4;                // (t % QUADS) * 4

    float acc[16][4];
#pragma unroll
    for (int oc = 0; oc < 16; oc++)
#pragma unroll
        for (int j = 0; j < 4; j++) acc[oc][j] = 0.f;

#pragma unroll 1
    for (int ic = 0; ic < 10; ic++) {
        const float* in = g_out1 + ic * P1H * P1H + y * P1H + x0;
        float r[3][6];
#pragma unroll
        for (int ky = 0; ky < 3; ky++)
#pragma unroll
            for (int kx = 0; kx < 6; kx++)
                r[ky][kx] = in[ky * P1H + kx];          // pad covers row-end overrun
#pragma unroll
        for (int oc = 0; oc < 16; oc++) {
            const float* w = &sw[(oc * 10 + ic) * 9];
#pragma unroll
            for (int ky = 0; ky < 3; ky++)
#pragma unroll
                for (int kx = 0; kx < 3; kx++) {
                    float ww = w[ky * 3 + kx];
                    acc[oc][0] += ww * r[ky][kx];
                    acc[oc][1] += ww * r[ky][kx + 1];
                    acc[oc][2] += ww * r[ky][kx + 2];
                    acc[oc][3] += ww * r[ky][kx + 3];
                }
        }
    }
#pragma unroll
    for (int oc = 0; oc < 16; oc++) {
        float b = sb[oc], p = sp[oc];
        float* o = g_out2 + oc * C2H * C2H + y * C2H + x0;
#pragma unroll
        for (int j = 0; j < 4; j++) {
            float v = acc[oc][j] + b;
            v = v >= 0.f ? v : p * v;
            if (x0 + j < C2H) o[j] = v;    // guard is load-bearing: avoids aliasing next row
        }
    }
}

// ---- kernel 3: conv3(3x3,16->32)+PReLU + 1x1 heads + softmax + compact ----------
__global__ __launch_bounds__(256) void k_conv3(const float* __restrict__ w3,
                                               const float* __restrict__ b3,
                                               const float* __restrict__ p3,
                                               const float* __restrict__ wa,
                                               const float* __restrict__ ba,
                                               const float* __restrict__ wb,
                                               const float* __restrict__ bb) {
    __shared__ float sw[4608];
    __shared__ float sb[32], sp[32], swa[64], sba[2], swb[128], sbb[4];
    int tid = threadIdx.x;
    for (int i = tid; i < 4608; i += 256) sw[i] = w3[i];
    if (tid < 32) { sb[tid] = b3[tid]; sp[tid] = p3[tid]; }
    if (tid < 64) swa[tid] = wa[tid];
    if (tid < 2)  sba[tid] = ba[tid];
    if (tid < 128) swb[tid] = wb[tid];
    if (tid < 4)  sbb[tid] = bb[tid];
    __syncthreads();

    const int PAIRS = (C3H + 1) / 2;   // 510
    int t = blockIdx.x * 256 + tid;
    if (t >= C3H * PAIRS) return;
    int y = t / PAIRS, pp = t % PAIRS;
    int x0 = pp * 2;

    float acc[32][2];
#pragma unroll
    for (int oc = 0; oc < 32; oc++) { acc[oc][0] = 0.f; acc[oc][1] = 0.f; }

#pragma unroll 1
    for (int ic = 0; ic < 16; ic++) {
        const float* in = g_out2 + ic * C2H * C2H + y * C2H + x0;
        float r[3][4];
#pragma unroll
        for (int ky = 0; ky < 3; ky++)
#pragma unroll
            for (int kx = 0; kx < 4; kx++)
                r[ky][kx] = in[ky * C2H + kx];
#pragma unroll
        for (int oc = 0; oc < 32; oc++) {
            const float* w = &sw[(oc * 16 + ic) * 9];
#pragma unroll
            for (int ky = 0; ky < 3; ky++)
#pragma unroll
                for (int kx = 0; kx < 3; kx++) {
                    float ww = w[ky * 3 + kx];
                    acc[oc][0] += ww * r[ky][kx];
                    acc[oc][1] += ww * r[ky][kx + 1];
                }
        }
    }

#pragma unroll
    for (int px = 0; px < 2; px++) {
        int x = x0 + px;
        if (x >= C3H) break;
        float c0 = sba[0], c1 = sba[1];
        float r0 = sbb[0], r1 = sbb[1], r2 = sbb[2], r3 = sbb[3];
#pragma unroll
        for (int c = 0; c < 32; c++) {
            float v = acc[c][px] + sb[c];
            float h = v >= 0.f ? v : sp[c] * v;
            c0 += swa[c]      * h;
            c1 += swa[32 + c] * h;
            r0 += swb[c]      * h;
            r1 += swb[32 + c] * h;
            r2 += swb[64 + c] * h;
            r3 += swb[96 + c] * h;
        }
        float prob = 1.0f / (1.0f + expf(c0 - c1));   // softmax[...,1]; expf kept exact-ish on purpose
        if (prob >= 0.6f) {
            int pos = atomicAdd(&g_cnt, 1);
            float* cb = g_cand + (size_t)pos * 6;
            cb[0] = prob;
            ((int*)cb)[1] = y * C3H + x;
            cb[2] = r0; cb[3] = r1; cb[4] = r2; cb[5] = r3;
        }
    }
}

// ---------------- kernel 4: exact top-512 sort + box decode + 2x NMS ------------
__device__ __forceinline__ unsigned long long pack_key(float s, int idx) {
    // descending score, then ascending index (matches jax.lax.top_k tiebreak)
    return ((unsigned long long)__float_as_uint(s) << 32) |
           (unsigned long long)(0xFFFFFFFFu - (unsigned)idx);
}

__global__ __launch_bounds__(1024) void k_topk_nms(float* __restrict__ out) {
    __shared__ unsigned long long s_key[NSORT];   // 16 KB (aliased as 4096-bin hist)
    __shared__ int   s_pos[NSORT];                // 8 KB
    __shared__ float s_bx1[KTOP], s_by1[KTOP], s_bx2[KTOP], s_by2[KTOP];
    __shared__ float s_area[KTOP], s_sc[KTOP];
    __shared__ int   s_keep[KTOP];
    __shared__ int   s_sel, s_bcut;

    int tid = threadIdx.x;
    int n = g_cnt;

    if (n <= NSORT) {
        for (int i = tid; i < NSORT; i += 1024) {
            if (i < n) {
                float s = g_cand[(size_t)i * 6];
                int idx = ((const int*)g_cand)[(size_t)i * 6 + 1];
                s_key[i] = pack_key(s, idx);
                s_pos[i] = i;
            } else { s_key[i] = 0ull; s_pos[i] = -1; }
        }
    } else {
        // histogram fallback: find score cutoff so selected count fits in NSORT
        int* hist = (int*)s_key;               // 4096 bins over [0.6, 1.0]
        for (int i = tid; i < 4096; i += 1024) hist[i] = 0;
        if (tid == 0) s_sel = 0;
        __syncthreads();
        for (int i = tid; i < n; i += 1024) {
            float s = g_cand[(size_t)i * 6];
            int b = (int)((s - 0.6f) * (4096.0f / 0.4f));
            b = b < 0 ? 0 : (b > 4095 ? 4095 : b);
            atomicAdd(&hist[b], 1);
        }
        __syncthreads();
        if (tid == 0) {
            int c = 0, bc = 0;
            for (int b = 4095; b >= 0; --b) { c += hist[b]; if (c >= KTOP) { bc = b; break; } }
            s_bcut = bc;
        }
        __syncthreads();
        int bcut = s_bcut;
        __syncthreads();                       // done with hist before clobbering keys
        for (int i = tid; i < NSORT; i += 1024) { s_key[i] = 0ull; s_pos[i] = -1; }
        __syncthreads();
        for (int i = tid; i < n; i += 1024) {
            float s = g_cand[(size_t)i * 6];
            int b = (int)((s - 0.6f) * (4096.0f / 0.4f));
            b = b < 0 ? 0 : (b > 4095 ? 4095 : b);
            if (b >= bcut) {
                int j = atomicAdd(&s_sel, 1);
                if (j < NSORT) {
                    int idx = ((const int*)g_cand)[(size_t)i * 6 + 1];
                    s_key[j] = pack_key(s, idx);
                    s_pos[j] = i;
                }
            }
        }
    }
    __syncthreads();

    // bitonic sort, descending by 64-bit key
    for (int k = 2; k <= NSORT; k <<= 1) {
        for (int j = k >> 1; j > 0; j >>= 1) {
            for (int i = tid; i < NSORT; i += 1024) {
                int ixj = i ^ j;
                if (ixj > i) {
                    bool down = ((i & k) == 0);
                    unsigned long long a = s_key[i], b = s_key[ixj];
                    if ((a < b) == down) {
                        s_key[i] = b; s_key[ixj] = a;
                        int tp = s_pos[i]; s_pos[i] = s_pos[ixj]; s_pos[ixj] = tp;
                    }
                }
            }
            __syncthreads();
        }
    }

    // decode boxes for top-512
    float bx1 = 0.f, by1 = 0.f, bx2 = 0.f, by2 = 0.f, area = 0.f, sc = 0.f;
    if (tid < KTOP) {
        unsigned long long key = s_key[tid];
        int pos = s_pos[tid];
        sc = __uint_as_float((unsigned)(key >> 32));
        int keep = 0;
        if (pos >= 0 && sc >= 0.6f) {
            const float* cb = g_cand + (size_t)pos * 6;
            int idx = ((const int*)cb)[1];
            float yy = (float)(idx / C3H);
            float xx = (float)(idx % C3H);
            float cx = (xx * 2.0f + 6.0f) / 0.6f;    // off_x == 6 for W=2048
            float cy = (yy * 2.0f + 6.0f) / 0.6f;
            const float wwn = 12.0f / 0.6f;          // 20
            bx1 = cx - wwn * 0.5f + cb[2] * wwn;
            by1 = cy - wwn * 0.5f + cb[3] * wwn;
            bx2 = cx + wwn * 0.5f + cb[4] * wwn;
            by2 = cy + wwn * 0.5f + cb[5] * wwn;
            area = (bx2 - bx1) * (by2 - by1);
            keep = 1;
        }
        s_bx1[tid] = bx1; s_by1[tid] = by1; s_bx2[tid] = bx2; s_by2[tid] = by2;
        s_area[tid] = area; s_sc[tid] = sc; s_keep[tid] = keep;
    }

    // two sequential NMS passes (thr 0.5, then 0.7), exact fori_loop semantics
#pragma unroll 1
    for (int pass = 0; pass < 2; pass++) {
        float thr = (pass == 0) ? 0.5f : 0.7f;
#pragma unroll 1
        for (int i = 0; i < KTOP; i++) {
            __syncthreads();
            if (tid < KTOP && tid > i && s_keep[i]) {
                float xi1 = fmaxf(s_bx1[i], bx1);
                float yi1 = fmaxf(s_by1[i], by1);
                float xi2 = fminf(s_bx2[i], bx2);
                float yi2 = fminf(s_by2[i], by2);
                float iw = fmaxf(xi2 - xi1, 0.0f);
                float ih = fmaxf(yi2 - yi1, 0.0f);
                float inter = iw * ih;
                float iou = inter / (s_area[i] + area - inter + 1e-9f);
                if (iou > thr) s_keep[tid] = 0;
            }
        }
        __syncthreads();
    }

    if (tid < KTOP) {
        float* o = out + tid * 5;
        if (s_keep[tid]) {
            o[0] = bx1; o[1] = by1; o[2] = bx2; o[3] = by2; o[4] = sc;
        } else {
            o[0] = 0.f; o[1] = 0.f; o[2] = 0.f; o[3] = 0.f; o[4] = 0.f;
        }
    }
}

// ---------------------------------- launch --------------------------------------
extern "C" void kernel_launch(void* const* d_in, const int* in_sizes, int n_in,
                              void* d_out, int out_size) {
    const float* x  = (const float*)d_in[0];
    const float* w1 = (const float*)d_in[1];
    const float* b1 = (const float*)d_in[2];
    const float* p1 = (const float*)d_in[3];
    const float* w2 = (const float*)d_in[4];
    const float* b2 = (const float*)d_in[5];
    const float* p2 = (const float*)d_in[6];
    const float* w3 = (const float*)d_in[7];
    const float* b3 = (const float*)d_in[8];
    const float* p3 = (const float*)d_in[9];
    const float* wa = (const float*)d_in[10];
    const float* ba = (const float*)d_in[11];
    const float* wb = (const float*)d_in[12];
    const float* bb = (const float*)d_in[13];

    int t1 = P1H * P1H;
    k_conv1<<<(t1 + 255) / 256, 256>>>(x, w1, b1, p1);   // also resets g_cnt

    int t2 = C2H * 256;   // 4 px/thread, QUADS = 256
    k_conv2<<<(t2 + 255) / 256, 256>>>(w2, b2, p2);

    int t3 = C3H * ((C3H + 1) / 2);
    k_conv3<<<(t3 + 255) / 256, 256>>>(w3, b3, p3, wa, ba, wb, bb);

    k_topk_nms<<<1, 1024>>>((float*)d_out);
}

// round 10
// speedup vs baseline: 1.2766x; 1.2766x over previous
#include <cuda_runtime.h>

// ---------------- problem constants (fixed shapes per reference) ----------------
#define IN_H 2048
#define IN_W 2048
#define P1H  1023           // after conv1 (2046) + 2x2 maxpool
#define C2H  1021           // after conv2
#define C3H  1019           // after conv3 / heads
#define NF   (C3H * C3H)    // 1038361 feature-map pixels
#define KTOP 512
#define NSORT 2048
#define NBINS 4096

// ---------------- scratch (static __device__, no allocations) -------------------
__device__ float g_out1[10 * P1H * P1H + 64];   // +pad: edge threads read a few cols past row end
__device__ float g_out2[16 * C2H * C2H + 64];
__device__ float g_cand[NF * 6];                // {score, idx(int bits), r0,r1,r2,r3}
__device__ float g_sel[NSORT * 6];              // compacted candidates above cutoff
__device__ int   g_hist[NBINS];
__device__ int   g_cnt;
__device__ int   g_selcnt;
__device__ int   g_bcut;

__device__ __forceinline__ int score_bin(float s) {
    int b = (int)((s - 0.6f) * (4096.0f / 0.4f));
    return b < 0 ? 0 : (b > 4095 ? 4095 : b);
}

// ---------------- kernel 1: conv1(3x3,3->10) + PReLU + maxpool 2x2 --------------
// Also resets counters + histogram (safe: consumed only by later stream-ordered kernels).
__global__ __launch_bounds__(256) void k_conv1(const float* __restrict__ x,
                                               const float* __restrict__ w1,
                                               const float* __restrict__ b1,
                                               const float* __restrict__ p1) {
    int gid = blockIdx.x * 256 + threadIdx.x;
    if (gid < NBINS) g_hist[gid] = 0;
    if (gid == 0) { g_cnt = 0; g_selcnt = 0; }

    __shared__ float sw[270], sb[10], sp[10];
    int tid = threadIdx.x;
    for (int i = tid; i < 270; i += 256) sw[i] = w1[i];
    if (tid < 10) { sb[tid] = b1[tid]; sp[tid] = p1[tid]; }
    __syncthreads();

    int t = blockIdx.x * 256 + tid;
    if (t >= P1H * P1H) return;
    int py = t / P1H, px = t % P1H;
    int iy = py * 2, ix = px * 2;

    float patch[3][4][4];
#pragma unroll
    for (int ic = 0; ic < 3; ic++)
#pragma unroll
        for (int r = 0; r < 4; r++)
#pragma unroll
            for (int c = 0; c < 4; c++)
                patch[ic][r][c] = x[ic * IN_H * IN_W + (iy + r) * IN_W + (ix + c)];

#pragma unroll
    for (int oc = 0; oc < 10; oc++) {
        float a0 = 0.f, a1 = 0.f, a2 = 0.f, a3 = 0.f;
#pragma unroll
        for (int ic = 0; ic < 3; ic++)
#pragma unroll
            for (int ky = 0; ky < 3; ky++)
#pragma unroll
                for (int kx = 0; kx < 3; kx++) {
                    float w = sw[((oc * 3 + ic) * 3 + ky) * 3 + kx];
                    a0 += w * patch[ic][ky][kx];
                    a1 += w * patch[ic][ky][kx + 1];
                    a2 += w * patch[ic][ky + 1][kx];
                    a3 += w * patch[ic][ky + 1][kx + 1];
                }
        float b = sb[oc], p = sp[oc];
        a0 += b; a1 += b; a2 += b; a3 += b;
        a0 = a0 >= 0.f ? a0 : p * a0;
        a1 = a1 >= 0.f ? a1 : p * a1;
        a2 = a2 >= 0.f ? a2 : p * a2;
        a3 = a3 >= 0.f ? a3 : p * a3;
        float m = fmaxf(fmaxf(a0, a1), fmaxf(a2, a3));
        g_out1[oc * P1H * P1H + t] = m;
    }
}

// ---------------- kernel 2: conv2(3x3,10->16) + PReLU (4 px/thread) -------------
__global__ __launch_bounds__(256) void k_conv2(const float* __restrict__ w2,
                                               const float* __restrict__ b2,
                                               const float* __restrict__ p2) {
    __shared__ float sw[1440], sb[16], sp[16];
    int tid = threadIdx.x;
    for (int i = tid; i < 1440; i += 256) sw[i] = w2[i];
    if (tid < 16) { sb[tid] = b2[tid]; sp[tid] = p2[tid]; }
    __syncthreads();

    const int QUADS = 256;                 // (C2H + 3) / 4
    int t = blockIdx.x * 256 + tid;
    if (t >= C2H * QUADS) return;
    int y = t >> 8;
    int x0 = (t & 255) * 4;

    float acc[16][4];
#pragma unroll
    for (int oc = 0; oc < 16; oc++)
#pragma unroll
        for (int j = 0; j < 4; j++) acc[oc][j] = 0.f;

#pragma unroll 1
    for (int ic = 0; ic < 10; ic++) {
        const float* in = g_out1 + ic * P1H * P1H + y * P1H + x0;
        float r[3][6];
#pragma unroll
        for (int ky = 0; ky < 3; ky++)
#pragma unroll
            for (int kx = 0; kx < 6; kx++)
                r[ky][kx] = in[ky * P1H + kx];
#pragma unroll
        for (int oc = 0; oc < 16; oc++) {
            const float* w = &sw[(oc * 10 + ic) * 9];
#pragma unroll
            for (int ky = 0; ky < 3; ky++)
#pragma unroll
                for (int kx = 0; kx < 3; kx++) {
                    float ww = w[ky * 3 + kx];
                    acc[oc][0] += ww * r[ky][kx];
                    acc[oc][1] += ww * r[ky][kx + 1];
                    acc[oc][2] += ww * r[ky][kx + 2];
                    acc[oc][3] += ww * r[ky][kx + 3];
                }
        }
    }
#pragma unroll
    for (int oc = 0; oc < 16; oc++) {
        float b = sb[oc], p = sp[oc];
        float* o = g_out2 + oc * C2H * C2H + y * C2H + x0;
#pragma unroll
        for (int j = 0; j < 4; j++) {
            float v = acc[oc][j] + b;
            v = v >= 0.f ? v : p * v;
            if (x0 + j < C2H) o[j] = v;
        }
    }
}

// ---- kernel 3: conv3(3x3,16->32)+PReLU + 1x1 heads + softmax + compact + hist ---
__global__ __launch_bounds__(256) void k_conv3(const float* __restrict__ w3,
                                               const float* __restrict__ b3,
                                               const float* __restrict__ p3,
                                               const float* __restrict__ wa,
                                               const float* __restrict__ ba,
                                               const float* __restrict__ wb,
                                               const float* __restrict__ bb) {
    __shared__ float sw[4608];
    __shared__ float sb[32], sp[32], swa[64], sba[2], swb[128], sbb[4];
    int tid = threadIdx.x;
    for (int i = tid; i < 4608; i += 256) sw[i] = w3[i];
    if (tid < 32) { sb[tid] = b3[tid]; sp[tid] = p3[tid]; }
    if (tid < 64) swa[tid] = wa[tid];
    if (tid < 2)  sba[tid] = ba[tid];
    if (tid < 128) swb[tid] = wb[tid];
    if (tid < 4)  sbb[tid] = bb[tid];
    __syncthreads();

    const int PAIRS = (C3H + 1) / 2;   // 510
    int t = blockIdx.x * 256 + tid;
    if (t >= C3H * PAIRS) return;
    int y = t / PAIRS, pp = t % PAIRS;
    int x0 = pp * 2;

    float acc[32][2];
#pragma unroll
    for (int oc = 0; oc < 32; oc++) { acc[oc][0] = 0.f; acc[oc][1] = 0.f; }

#pragma unroll 1
    for (int ic = 0; ic < 16; ic++) {
        const float* in = g_out2 + ic * C2H * C2H + y * C2H + x0;
        float r[3][4];
#pragma unroll
        for (int ky = 0; ky < 3; ky++)
#pragma unroll
            for (int kx = 0; kx < 4; kx++)
                r[ky][kx] = in[ky * C2H + kx];
#pragma unroll
        for (int oc = 0; oc < 32; oc++) {
            const float* w = &sw[(oc * 16 + ic) * 9];
#pragma unroll
            for (int ky = 0; ky < 3; ky++)
#pragma unroll
                for (int kx = 0; kx < 3; kx++) {
                    float ww = w[ky * 3 + kx];
                    acc[oc][0] += ww * r[ky][kx];
                    acc[oc][1] += ww * r[ky][kx + 1];
                }
        }
    }

#pragma unroll
    for (int px = 0; px < 2; px++) {
        int x = x0 + px;
        if (x >= C3H) break;
        float c0 = sba[0], c1 = sba[1];
        float r0 = sbb[0], r1 = sbb[1], r2 = sbb[2], r3 = sbb[3];
#pragma unroll
        for (int c = 0; c < 32; c++) {
            float v = acc[c][px] + sb[c];
            float h = v >= 0.f ? v : sp[c] * v;
            c0 += swa[c]      * h;
            c1 += swa[32 + c] * h;
            r0 += swb[c]      * h;
            r1 += swb[32 + c] * h;
            r2 += swb[64 + c] * h;
            r3 += swb[96 + c] * h;
        }
        float prob = 1.0f / (1.0f + expf(c0 - c1));   // softmax[...,1]
        if (prob >= 0.6f) {
            atomicAdd(&g_hist[score_bin(prob)], 1);
            int pos = atomicAdd(&g_cnt, 1);
            float* cb = g_cand + (size_t)pos * 6;
            cb[0] = prob;
            ((int*)cb)[1] = y * C3H + x;
            cb[2] = r0; cb[3] = r1; cb[4] = r2; cb[5] = r3;
        }
    }
}

// ---------------- kernel 4a: cutoff bin from global histogram -------------------
__global__ __launch_bounds__(1024) void k_cutoff() {
    __shared__ int h[NBINS];
    __shared__ int chunk[1024];
    int tid = threadIdx.x;
    for (int i = tid; i < NBINS; i += 1024) h[i] = g_hist[i];
    __syncthreads();
    chunk[tid] = h[tid * 4] + h[tid * 4 + 1] + h[tid * 4 + 2] + h[tid * 4 + 3];
    __syncthreads();
    if (tid == 0) {
        int bc = 0;
        if (g_cnt > NSORT) {
            int c = 0, ci = 1023;
            for (; ci >= 0; --ci) { c += chunk[ci]; if (c >= KTOP) break; }
            if (ci >= 0) {
                int cnt = c - chunk[ci];
                int bb = 4 * ci + 3;
                for (; bb >= 4 * ci; --bb) { cnt += h[bb]; if (cnt >= KTOP) break; }
                bc = (cnt >= KTOP) ? bb : 0;   // inner break guaranteed; guard anyway
            }
        }
        g_bcut = bc;
    }
}

// ---------------- kernel 4b: grid-wide compaction of candidates -----------------
__global__ __launch_bounds__(256) void k_select() {
    int i = blockIdx.x * 256 + threadIdx.x;
    if (i >= g_cnt) return;
    float s = g_cand[(size_t)i * 6];
    if (score_bin(s) >= g_bcut) {
        int j = atomicAdd(&g_selcnt, 1);
        if (j < NSORT) {
#pragma unroll
            for (int k = 0; k < 6; k++)
                g_sel[j * 6 + k] = g_cand[(size_t)i * 6 + k];
        }
    }
}

// -------- kernel 5: sort <=2048 + box decode + bitmask NMS (two thresholds) -----
__device__ __forceinline__ unsigned long long pack_key(float s, int idx) {
    // descending score, then ascending index (matches jax.lax.top_k tiebreak)
    return ((unsigned long long)__float_as_uint(s) << 32) |
           (unsigned long long)(0xFFFFFFFFu - (unsigned)idx);
}

__global__ __launch_bounds__(1024) void k_topk_nms(float* __restrict__ out) {
    // phase-overlaid shared buffer:
    //   sort:  keys [0,16384), pos [16384,24576)
    //   nms:   x1/y1/x2/y2/area @0..10240, keep @10240, sup-matrix @12288 (+32768)
    __shared__ __align__(16) unsigned char BUF[45056];
    __shared__ unsigned int s_kw[16];

    unsigned long long* keys = (unsigned long long*)BUF;
    int* pos = (int*)(BUF + 16384);

    int tid = threadIdx.x;
    int m = g_selcnt; if (m > NSORT) m = NSORT;

    for (int i = tid; i < NSORT; i += 1024) {
        if (i < m) {
            float s = g_sel[i * 6];
            int idx = ((const int*)g_sel)[i * 6 + 1];
            keys[i] = pack_key(s, idx);
            pos[i] = i;
        } else { keys[i] = 0ull; pos[i] = -1; }
    }
    __syncthreads();

    // bitonic sort, descending by 64-bit key
    for (int k = 2; k <= NSORT; k <<= 1) {
        for (int j = k >> 1; j > 0; j >>= 1) {
            for (int i = tid; i < NSORT; i += 1024) {
                int ixj = i ^ j;
                if (ixj > i) {
                    bool down = ((i & k) == 0);
                    unsigned long long a = keys[i], b = keys[ixj];
                    if ((a < b) == down) {
                        keys[i] = b; keys[ixj] = a;
                        int tp = pos[i]; pos[i] = pos[ixj]; pos[ixj] = tp;
                    }
                }
            }
            __syncthreads();
        }
    }

    // decode top-512 into registers (same formulas as reference)
    float bx1 = 0.f, by1 = 0.f, bx2 = 0.f, by2 = 0.f, area = 0.f, sc = 0.f;
    int keep = 0;
    if (tid < KTOP) {
        unsigned long long key = keys[tid];
        int p = pos[tid];
        sc = __uint_as_float((unsigned)(key >> 32));
        if (p >= 0 && sc >= 0.6f) {
            const float* cb = g_sel + (size_t)p * 6;
            int idx = ((const int*)cb)[1];
            float yy = (float)(idx / C3H);
            float xx = (float)(idx % C3H);
            float cx = (xx * 2.0f + 6.0f) / 0.6f;
            float cy = (yy * 2.0f + 6.0f) / 0.6f;
            const float wwn = 12.0f / 0.6f;
            bx1 = cx - wwn * 0.5f + cb[2] * wwn;
            by1 = cy - wwn * 0.5f + cb[3] * wwn;
            bx2 = cx + wwn * 0.5f + cb[4] * wwn;
            by2 = cy + wwn * 0.5f + cb[5] * wwn;
            area = (bx2 - bx1) * (by2 - by1);
            keep = 1;
        }
    }
    __syncthreads();          // all reads of keys/pos done before overlay

    float* sx1 = (float*)BUF;
    float* sy1 = (float*)(BUF + 2048);
    float* sx2 = (float*)(BUF + 4096);
    float* sy2 = (float*)(BUF + 6144);
    float* sar = (float*)(BUF + 8192);
    int*   skp = (int*)(BUF + 10240);
    unsigned int* sup = (unsigned int*)(BUF + 12288);   // 512 rows x 16 words

    if (tid < KTOP) {
        sx1[tid] = bx1; sy1[tid] = by1; sx2[tid] = bx2; sy2[tid] = by2;
        sar[tid] = area; skp[tid] = keep;
    }
    __syncthreads();

    if (tid == 0) {
#pragma unroll 1
        for (int w = 0; w < 16; w++) {
            unsigned int v = 0;
            for (int l = 0; l < 32; l++) v |= (unsigned)(skp[w * 32 + l] != 0) << l;
            s_kw[w] = v;
        }
    }

    // two NMS passes (thr 0.5 then 0.7). Suppression matrix is static per pass
    // (iou independent of keep), so greedy walk == fori_loop semantics exactly.
#pragma unroll 1
    for (int pass = 0; pass < 2; pass++) {
        float thr = (pass == 0) ? 0.5f : 0.7f;
        __syncthreads();
        {   // 2 threads per row: tid>>1 = row, (tid&1)*8 = word offset
            int i = tid >> 1;
            int w0 = (tid & 1) * 8;
            float a1 = sx1[i], a2 = sy1[i], a3 = sx2[i], a4 = sy2[i], aa = sar[i];
#pragma unroll 1
            for (int w = w0; w < w0 + 8; w++) {
                unsigned int bits = 0;
#pragma unroll
                for (int l = 0; l < 32; l++) {
                    int j = w * 32 + l;
                    float xi1 = fmaxf(a1, sx1[j]);
                    float yi1 = fmaxf(a2, sy1[j]);
                    float xi2 = fminf(a3, sx2[j]);
                    float yi2 = fminf(a4, sy2[j]);
                    float iw = fmaxf(xi2 - xi1, 0.0f);
                    float ih = fmaxf(yi2 - yi1, 0.0f);
                    float inter = iw * ih;
                    float iou = inter / (aa + sar[j] - inter + 1e-9f);
                    bits |= ((iou > thr) && (j > i)) ? (1u << l) : 0u;
                }
                sup[i * 16 + w] = bits;
            }
        }
        __syncthreads();
        if (tid == 0) {
            unsigned int kw[16];
#pragma unroll
            for (int w = 0; w < 16; w++) kw[w] = s_kw[w];
#pragma unroll 1
            for (int i = 0; i < KTOP; i++) {
                if ((kw[i >> 5] >> (i & 31)) & 1u) {
#pragma unroll
                    for (int w = 0; w < 16; w++) kw[w] &= ~sup[i * 16 + w];
                }
            }
#pragma unroll
            for (int w = 0; w < 16; w++) s_kw[w] = kw[w];
        }
    }
    __syncthreads();

    if (tid < KTOP) {
        int kp = (s_kw[tid >> 5] >> (tid & 31)) & 1u;
        float* o = out + tid * 5;
        if (kp) { o[0] = bx1; o[1] = by1; o[2] = bx2; o[3] = by2; o[4] = sc; }
        else    { o[0] = 0.f; o[1] = 0.f; o[2] = 0.f; o[3] = 0.f; o[4] = 0.f; }
    }
}

// ---------------------------------- launch --------------------------------------
extern "C" void kernel_launch(void* const* d_in, const int* in_sizes, int n_in,
                              void* d_out, int out_size) {
    const float* x  = (const float*)d_in[0];
    const float* w1 = (const float*)d_in[1];
    const float* b1 = (const float*)d_in[2];
    const float* p1 = (const float*)d_in[3];
    const float* w2 = (const float*)d_in[4];
    const float* b2 = (const float*)d_in[5];
    const float* p2 = (const float*)d_in[6];
    const float* w3 = (const float*)d_in[7];
    const float* b3 = (const float*)d_in[8];
    const float* p3 = (const float*)d_in[9];
    const float* wa = (const float*)d_in[10];
    const float* ba = (const float*)d_in[11];
    const float* wb = (const float*)d_in[12];
    const float* bb = (const float*)d_in[13];

    int t1 = P1H * P1H;
    k_conv1<<<(t1 + 255) / 256, 256>>>(x, w1, b1, p1);   // also zeroes hist/counters

    int t2 = C2H * 256;
    k_conv2<<<(t2 + 255) / 256, 256>>>(w2, b2, p2);

    int t3 = C3H * ((C3H + 1) / 2);
    k_conv3<<<(t3 + 255) / 256, 256>>>(w3, b3, p3, wa, ba, wb, bb);

    k_cutoff<<<1, 1024>>>();
    k_select<<<(NF + 255) / 256, 256>>>();
    k_topk_nms<<<1, 1024>>>((float*)d_out);
}

// round 14
// speedup vs baseline: 1.4948x; 1.1709x over previous
#include <cuda_runtime.h>

// ---------------- problem constants (fixed shapes per reference) ----------------
#define IN_H 2048
#define IN_W 2048
#define P1H  1023
#define C2H  1021
#define C3H  1019
#define NF   (C3H * C3H)
#define KTOP 512
#define NSORT 2048
#define NBINS 4096
#define FULLM 0xFFFFFFFFu

// ---------------- scratch (static __device__, no allocations) -------------------
__device__ float g_out1[10 * P1H * P1H + 64];
__device__ float g_out2[16 * C2H * C2H + 64];
__device__ float g_cand[NF * 6];
__device__ float g_sel[NSORT * 6];
__device__ int   g_hist[NBINS];
__device__ int   g_cnt;
__device__ int   g_selcnt;
__device__ int   g_bcut;

__device__ __forceinline__ int score_bin(float s) {
    int b = (int)((s - 0.6f) * (4096.0f / 0.4f));
    return b < 0 ? 0 : (b > 4095 ? 4095 : b);
}

// ---------------- kernel 1: conv1(3x3,3->10) + PReLU + maxpool 2x2 --------------
__global__ __launch_bounds__(256) void k_conv1(const float* __restrict__ x,
                                               const float* __restrict__ w1,
                                               const float* __restrict__ b1,
                                               const float* __restrict__ p1) {
    int gid = blockIdx.x * 256 + threadIdx.x;
    if (gid < NBINS) g_hist[gid] = 0;
    if (gid == 0) { g_cnt = 0; g_selcnt = 0; }

    __shared__ float sw[270], sb[10], sp[10];
    int tid = threadIdx.x;
    for (int i = tid; i < 270; i += 256) sw[i] = w1[i];
    if (tid < 10) { sb[tid] = b1[tid]; sp[tid] = p1[tid]; }
    __syncthreads();

    int t = blockIdx.x * 256 + tid;
    if (t >= P1H * P1H) return;
    int py = t / P1H, px = t % P1H;
    int iy = py * 2, ix = px * 2;

    float patch[3][4][4];
#pragma unroll
    for (int ic = 0; ic < 3; ic++)
#pragma unroll
        for (int r = 0; r < 4; r++)
#pragma unroll
            for (int c = 0; c < 4; c++)
                patch[ic][r][c] = x[ic * IN_H * IN_W + (iy + r) * IN_W + (ix + c)];

#pragma unroll
    for (int oc = 0; oc < 10; oc++) {
        float a0 = 0.f, a1 = 0.f, a2 = 0.f, a3 = 0.f;
#pragma unroll
        for (int ic = 0; ic < 3; ic++)
#pragma unroll
            for (int ky = 0; ky < 3; ky++)
#pragma unroll
                for (int kx = 0; kx < 3; kx++) {
                    float w = sw[((oc * 3 + ic) * 3 + ky) * 3 + kx];
                    a0 += w * patch[ic][ky][kx];
                    a1 += w * patch[ic][ky][kx + 1];
                    a2 += w * patch[ic][ky + 1][kx];
                    a3 += w * patch[ic][ky + 1][kx + 1];
                }
        float b = sb[oc], p = sp[oc];
        a0 += b; a1 += b; a2 += b; a3 += b;
        a0 = a0 >= 0.f ? a0 : p * a0;
        a1 = a1 >= 0.f ? a1 : p * a1;
        a2 = a2 >= 0.f ? a2 : p * a2;
        a3 = a3 >= 0.f ? a3 : p * a3;
        float m = fmaxf(fmaxf(a0, a1), fmaxf(a2, a3));
        g_out1[oc * P1H * P1H + t] = m;
    }
}

// ---------------- kernel 2: conv2 (4 px/thread, float4 weight loads) ------------
__global__ __launch_bounds__(256) void k_conv2(const float* __restrict__ w2,
                                               const float* __restrict__ b2,
                                               const float* __restrict__ p2) {
    // weights padded to 12 floats per (oc,ic): 48B stride, 16B aligned -> LDS.128
    __shared__ __align__(16) float sw[16 * 10 * 12];
    __shared__ float sb[16], sp[16];
    int tid = threadIdx.x;
    for (int i = tid; i < 16 * 10 * 12; i += 256) {
        int oc = i / 120, r = i % 120, ic = r / 12, k = r % 12;
        sw[i] = (k < 9) ? w2[(oc * 10 + ic) * 9 + k] : 0.f;
    }
    if (tid < 16) { sb[tid] = b2[tid]; sp[tid] = p2[tid]; }
    __syncthreads();

    const int QUADS = 256;
    int t = blockIdx.x * 256 + tid;
    if (t >= C2H * QUADS) return;
    int y = t >> 8;
    int x0 = (t & 255) * 4;

    float acc[16][4];
#pragma unroll
    for (int oc = 0; oc < 16; oc++)
#pragma unroll
        for (int j = 0; j < 4; j++) acc[oc][j] = 0.f;

#pragma unroll 1
    for (int ic = 0; ic < 10; ic++) {
        const float* in = g_out1 + ic * P1H * P1H + y * P1H + x0;
        float r[3][6];
#pragma unroll
        for (int ky = 0; ky < 3; ky++)
#pragma unroll
            for (int kx = 0; kx < 6; kx++)
                r[ky][kx] = in[ky * P1H + kx];
#pragma unroll
        for (int oc = 0; oc < 16; oc++) {
            const float* wp = sw + (oc * 10 + ic) * 12;
            float4 wA = *(const float4*)wp;
            float4 wB = *(const float4*)(wp + 4);
            float  w8 = wp[8];
#pragma unroll
            for (int j = 0; j < 4; j++) {
                float a = acc[oc][j];
                a += wA.x * r[0][j]   + wA.y * r[0][j+1] + wA.z * r[0][j+2];
                a += wA.w * r[1][j]   + wB.x * r[1][j+1] + wB.y * r[1][j+2];
                a += wB.z * r[2][j]   + wB.w * r[2][j+1] + w8   * r[2][j+2];
                acc[oc][j] = a;
            }
        }
    }
#pragma unroll
    for (int oc = 0; oc < 16; oc++) {
        float b = sb[oc], p = sp[oc];
        float* o = g_out2 + oc * C2H * C2H + y * C2H + x0;
#pragma unroll
        for (int j = 0; j < 4; j++) {
            float v = acc[oc][j] + b;
            v = v >= 0.f ? v : p * v;
            if (x0 + j < C2H) o[j] = v;    // load-bearing: avoids aliasing next row
        }
    }
}

// ---- kernel 3: conv3 + heads + softmax + warp-aggregated compact + hist ---------
__global__ __launch_bounds__(256) void k_conv3(const float* __restrict__ w3,
                                               const float* __restrict__ b3,
                                               const float* __restrict__ p3,
                                               const float* __restrict__ wa,
                                               const float* __restrict__ ba,
                                               const float* __restrict__ wb,
                                               const float* __restrict__ bb) {
    __shared__ __align__(16) float sw[32 * 16 * 12];   // 24 KB, padded stride 12
    __shared__ float sb[32], sp[32], swa[64], sba[2], swb[128], sbb[4];
    int tid = threadIdx.x;
    for (int i = tid; i < 32 * 16 * 12; i += 256) {
        int oc = i / 192, r = i % 192, ic = r / 12, k = r % 12;
        sw[i] = (k < 9) ? w3[(oc * 16 + ic) * 9 + k] : 0.f;
    }
    if (tid < 32) { sb[tid] = b3[tid]; sp[tid] = p3[tid]; }
    if (tid < 64) swa[tid] = wa[tid];
    if (tid < 2)  sba[tid] = ba[tid];
    if (tid < 128) swb[tid] = wb[tid];
    if (tid < 4)  sbb[tid] = bb[tid];
    __syncthreads();

    const int PAIRS = (C3H + 1) / 2;   // 510
    int t = blockIdx.x * 256 + tid;
    bool alive = t < C3H * PAIRS;      // NO early return: warps stay whole for ballots
    int ts = alive ? t : 0;
    int y = ts / PAIRS, pp = ts % PAIRS;
    int x0 = pp * 2;
    int lane = tid & 31;

    float acc[32][2];
#pragma unroll
    for (int oc = 0; oc < 32; oc++) { acc[oc][0] = 0.f; acc[oc][1] = 0.f; }

#pragma unroll 1
    for (int ic = 0; ic < 16; ic++) {
        const float* in = g_out2 + ic * C2H * C2H + y * C2H + x0;
        float r[3][4];
#pragma unroll
        for (int ky = 0; ky < 3; ky++)
#pragma unroll
            for (int kx = 0; kx < 4; kx++)
                r[ky][kx] = in[ky * C2H + kx];
#pragma unroll
        for (int oc = 0; oc < 32; oc++) {
            const float* wp = sw + (oc * 16 + ic) * 12;
            float4 wA = *(const float4*)wp;
            float4 wB = *(const float4*)(wp + 4);
            float  w8 = wp[8];
#pragma unroll
            for (int j = 0; j < 2; j++) {
                float a = acc[oc][j];
                a += wA.x * r[0][j]   + wA.y * r[0][j+1] + wA.z * r[0][j+2];
                a += wA.w * r[1][j]   + wB.x * r[1][j+1] + wB.y * r[1][j+2];
                a += wB.z * r[2][j]   + wB.w * r[2][j+1] + w8   * r[2][j+2];
                acc[oc][j] = a;
            }
        }
    }

#pragma unroll
    for (int px = 0; px < 2; px++) {
        int x = x0 + px;
        float c0 = sba[0], c1 = sba[1];
        float r0 = sbb[0], r1 = sbb[1], r2 = sbb[2], r3 = sbb[3];
#pragma unroll
        for (int c = 0; c < 32; c++) {
            float v = acc[c][px] + sb[c];
            float h = v >= 0.f ? v : sp[c] * v;
            c0 += swa[c]      * h;
            c1 += swa[32 + c] * h;
            r0 += swb[c]      * h;
            r1 += swb[32 + c] * h;
            r2 += swb[64 + c] * h;
            r3 += swb[96 + c] * h;
        }
        float prob = 1.0f / (1.0f + expf(c0 - c1));
        bool pred = alive && (x < C3H) && (prob >= 0.6f);

        // warp-aggregated slot allocation: one atomicAdd per warp-px
        unsigned mask = __ballot_sync(FULLM, pred);
        int n = __popc(mask);
        if (n) {
            int leader = __ffs(mask) - 1;
            int base = 0;
            if (lane == leader) base = atomicAdd(&g_cnt, n);
            base = __shfl_sync(FULLM, base, leader);
            if (pred) {
                int pos = base + __popc(mask & ((1u << lane) - 1u));
                atomicAdd(&g_hist[score_bin(prob)], 1);   // spread-addr REDG: cheap
                float* cb = g_cand + (size_t)pos * 6;
                cb[0] = prob;
                ((int*)cb)[1] = y * C3H + x;
                cb[2] = r0; cb[3] = r1; cb[4] = r2; cb[5] = r3;
            }
        }
    }
}

// ---------------- kernel 4a: cutoff via parallel suffix scan --------------------
__global__ __launch_bounds__(1024) void k_cutoff() {
    __shared__ int h[NBINS];
    __shared__ int sA[1024], sB[1024];
    __shared__ int s_bc;
    int tid = threadIdx.x;
    for (int i = tid; i < NBINS; i += 1024) h[i] = g_hist[i];
    if (tid == 0) s_bc = 0;
    __syncthreads();
    sA[tid] = h[tid * 4] + h[tid * 4 + 1] + h[tid * 4 + 2] + h[tid * 4 + 3];
    __syncthreads();
    int* src = sA; int* dst = sB;
    for (int d = 1; d < 1024; d <<= 1) {       // inclusive suffix sums, 10 rounds
        int v = src[tid] + ((tid + d < 1024) ? src[tid + d] : 0);
        dst[tid] = v;
        __syncthreads();
        int* tp = src; src = dst; dst = tp;
    }
    if (g_cnt > NSORT) {
        int suffHere = src[tid];
        int suffNext = (tid + 1 < 1024) ? src[tid + 1] : 0;
        if (suffHere >= KTOP && suffNext < KTOP) {   // unique crossing chunk
            int cnt = suffNext, bc = 4 * tid;
            for (int b = 4 * tid + 3; b >= 4 * tid; --b) {
                cnt += h[b];
                if (cnt >= KTOP) { bc = b; break; }
            }
            s_bc = bc;
        }
    }
    __syncthreads();
    if (tid == 0) g_bcut = s_bc;
}

// ---------------- kernel 4b: grid-wide compaction -------------------------------
__global__ __launch_bounds__(256) void k_select() {
    int i = blockIdx.x * 256 + threadIdx.x;
    if (i >= g_cnt) return;
    float s = g_cand[(size_t)i * 6];
    if (score_bin(s) >= g_bcut) {
        int j = atomicAdd(&g_selcnt, 1);
        if (j < NSORT) {
#pragma unroll
            for (int k = 0; k < 6; k++)
                g_sel[j * 6 + k] = g_cand[(size_t)i * 6 + k];
        }
    }
}

// -------- kernel 5: sort <=2048 + box decode + bitmask NMS ----------------------
__device__ __forceinline__ unsigned long long pack_key(float s, int idx) {
    return ((unsigned long long)__float_as_uint(s) << 32) |
           (unsigned long long)(0xFFFFFFFFu - (unsigned)idx);
}

__global__ __launch_bounds__(1024) void k_topk_nms(float* __restrict__ out) {
    __shared__ __align__(16) unsigned char BUF[45056];
    __shared__ unsigned int s_kw[16];

    unsigned long long* keys = (unsigned long long*)BUF;
    int* pos = (int*)(BUF + 16384);

    int tid = threadIdx.x;
    int m = g_selcnt; if (m > NSORT) m = NSORT;

    for (int i = tid; i < NSORT; i += 1024) {
        if (i < m) {
            float s = g_sel[i * 6];
            int idx = ((const int*)g_sel)[i * 6 + 1];
            keys[i] = pack_key(s, idx);
            pos[i] = i;
        } else { keys[i] = 0ull; pos[i] = -1; }
    }
    __syncthreads();

    for (int k = 2; k <= NSORT; k <<= 1) {
        for (int j = k >> 1; j > 0; j >>= 1) {
            for (int i = tid; i < NSORT; i += 1024) {
                int ixj = i ^ j;
                if (ixj > i) {
                    bool down = ((i & k) == 0);
                    unsigned long long a = keys[i], b = keys[ixj];
                    if ((a < b) == down) {
                        keys[i] = b; keys[ixj] = a;
                        int tp = pos[i]; pos[i] = pos[ixj]; pos[ixj] = tp;
                    }
                }
            }
            __syncthreads();
        }
    }

    float bx1 = 0.f, by1 = 0.f, bx2 = 0.f, by2 = 0.f, area = 0.f, sc = 0.f;
    int keep = 0;
    if (tid < KTOP) {
        unsigned long long key = keys[tid];
        int p = pos[tid];
        sc = __uint_as_float((unsigned)(key >> 32));
        if (p >= 0 && sc >= 0.6f) {
            const float* cb = g_sel + (size_t)p * 6;
            int idx = ((const int*)cb)[1];
            float yy = (float)(idx / C3H);
            float xx = (float)(idx % C3H);
            float cx = (xx * 2.0f + 6.0f) / 0.6f;
            float cy = (yy * 2.0f + 6.0f) / 0.6f;
            const float wwn = 12.0f / 0.6f;
            bx1 = cx - wwn * 0.5f + cb[2] * wwn;
            by1 = cy - wwn * 0.5f + cb[3] * wwn;
            bx2 = cx + wwn * 0.5f + cb[4] * wwn;
            by2 = cy + wwn * 0.5f + cb[5] * wwn;
            area = (bx2 - bx1) * (by2 - by1);
            keep = 1;
        }
    }
    __syncthreads();

    float* sx1 = (float*)BUF;
    float* sy1 = (float*)(BUF + 2048);
    float* sx2 = (float*)(BUF + 4096);
    float* sy2 = (float*)(BUF + 6144);
    float* sar = (float*)(BUF + 8192);
    int*   skp = (int*)(BUF + 10240);
    unsigned int* sup = (unsigned int*)(BUF + 12288);   // 512 x 16 words

    if (tid < KTOP) {
        sx1[tid] = bx1; sy1[tid] = by1; sx2[tid] = bx2; sy2[tid] = by2;
        sar[tid] = area; skp[tid] = keep;
    }
    __syncthreads();

    if (tid < KTOP) {   // warp-parallel keep-word init: 16 warps, one word each
        unsigned v = __ballot_sync(FULLM, skp[tid] != 0);
        if ((tid & 31) == 0) s_kw[tid >> 5] = v;
    }

#pragma unroll 1
    for (int pass = 0; pass < 2; pass++) {
        float thr = (pass == 0) ? 0.5f : 0.7f;
        __syncthreads();
        {   // static suppression matrix: 2 threads/row
            int i = tid >> 1;
            int w0 = (tid & 1) * 8;
            float a1 = sx1[i], a2 = sy1[i], a3 = sx2[i], a4 = sy2[i], aa = sar[i];
#pragma unroll 1
            for (int w = w0; w < w0 + 8; w++) {
                unsigned int bits = 0;
#pragma unroll
                for (int l = 0; l < 32; l++) {
                    int j = w * 32 + l;
                    float xi1 = fmaxf(a1, sx1[j]);
                    float yi1 = fmaxf(a2, sy1[j]);
                    float xi2 = fminf(a3, sx2[j]);
                    float yi2 = fminf(a4, sy2[j]);
                    float iw = fmaxf(xi2 - xi1, 0.0f);
                    float ih = fmaxf(yi2 - yi1, 0.0f);
                    float inter = iw * ih;
                    float iou = inter / (aa + sar[j] - inter + 1e-9f);
                    bits |= ((iou > thr) && (j > i)) ? (1u << l) : 0u;
                }
                sup[i * 16 + w] = bits;
            }
        }
        __syncthreads();
        if (tid < 32) {   // warp 0: greedy walk, keep-words in registers per lane
            unsigned kw = (tid < 16) ? s_kw[tid] : 0u;
#pragma unroll 1
            for (int i = 0; i < KTOP; i++) {
                unsigned word = __shfl_sync(FULLM, kw, i >> 5);
                if ((word >> (i & 31)) & 1u) {
                    if (tid < 16) kw &= ~sup[i * 16 + tid];
                }
            }
            if (tid < 16) s_kw[tid] = kw;
        }
    }
    __syncthreads();

    if (tid < KTOP) {
        int kp = (s_kw[tid >> 5] >> (tid & 31)) & 1u;
        float* o = out + tid * 5;
        if (kp) { o[0] = bx1; o[1] = by1; o[2] = bx2; o[3] = by2; o[4] = sc; }
        else    { o[0] = 0.f; o[1] = 0.f; o[2] = 0.f; o[3] = 0.f; o[4] = 0.f; }
    }
}

// ---------------------------------- launch --------------------------------------
extern "C" void kernel_launch(void* const* d_in, const int* in_sizes, int n_in,
                              void* d_out, int out_size) {
    const float* x  = (const float*)d_in[0];
    const float* w1 = (const float*)d_in[1];
    const float* b1 = (const float*)d_in[2];
    const float* p1 = (const float*)d_in[3];
    const float* w2 = (const float*)d_in[4];
    const float* b2 = (const float*)d_in[5];
    const float* p2 = (const float*)d_in[6];
    const float* w3 = (const float*)d_in[7];
    const float* b3 = (const float*)d_in[8];
    const float* p3 = (const float*)d_in[9];
    const float* wa = (const float*)d_in[10];
    const float* ba = (const float*)d_in[11];
    const float* wb = (const float*)d_in[12];
    const float* bb = (const float*)d_in[13];

    int t1 = P1H * P1H;
    k_conv1<<<(t1 + 255) / 256, 256>>>(x, w1, b1, p1);

    int t2 = C2H * 256;
    k_conv2<<<(t2 + 255) / 256, 256>>>(w2, b2, p2);

    int t3 = C3H * ((C3H + 1) / 2);
    k_conv3<<<(t3 + 255) / 256, 256>>>(w3, b3, p3, wa, ba, wb, bb);

    k_cutoff<<<1, 1024>>>();
    k_select<<<(NF + 255) / 256, 256>>>();
    k_topk_nms<<<1, 1024>>>((float*)d_out);
}